// round 2
// baseline (speedup 1.0000x reference)
#include <cuda_runtime.h>
#include <stdint.h>

#define MAX_NODES 100000
#define MAX_EDGES 3200000
#define MAX_PAIRS 1000000
#define HID 64
#define OUTD 16

// Scratch (device globals — no allocation allowed)
__device__ float g_h [MAX_NODES * HID];    // (x@W1) * dis[row]   (pre-scaled)
__device__ float g_z [MAX_NODES * HID];    // relu(layer1 out)
__device__ float g_h2[MAX_NODES * OUTD];   // (z@W2) * dis[row]   (pre-scaled)
__device__ float g_z2[MAX_NODES * OUTD];   // layer2 out (final embeddings)
__device__ float g_dis[MAX_NODES];
__device__ int   g_counts[MAX_NODES];
__device__ int   g_off[MAX_NODES + 1];
__device__ int   g_cursor[MAX_NODES];
__device__ int   g_csr_src[MAX_EDGES];
__device__ int   g_src[MAX_EDGES];
__device__ int   g_dst[MAX_EDGES];
__device__ int   g_mode;                   // 0 = indices are int64, 1 = int32

// ---------------------------------------------------------------------------
// Detect whether index buffers are int64 or int32 (JAX x64 off -> int32).
__global__ void detect_kernel(const void* __restrict__ ei, int ne, int n) {
    if (threadIdx.x == 0 && blockIdx.x == 0) {
        const long long* p = (const long long*)ei;
        int k = ne < 256 ? ne : 256;
        int ok64 = 1;
        for (int i = 0; i < k; ++i) {
            long long v = p[i];
            if (v < 0 || v >= (long long)n) { ok64 = 0; break; }
        }
        g_mode = ok64 ? 0 : 1;
    }
}

// Normalize edge_index [2, ne] to int32 g_src/g_dst with clamping.
__global__ void convert_kernel(const void* __restrict__ ei, int ne, int n) {
    int i = blockIdx.x * blockDim.x + threadIdx.x;
    int tot = 2 * ne;
    if (i >= tot) return;
    int mode = g_mode;
    long long v;
    if (mode) v = (long long)((const int*)ei)[i];
    else      v = ((const long long*)ei)[i];
    if (v < 0) v = 0;
    if (v >= n) v = n - 1;
    int vi = (int)v;
    if (i < ne) g_src[i] = vi;
    else        g_dst[i - ne] = vi;
}

// ---------------------------------------------------------------------------
__global__ void zero_counts_kernel(int n) {
    int i = blockIdx.x * blockDim.x + threadIdx.x;
    if (i < n) g_counts[i] = 0;
}

__global__ void count_kernel(int ne) {
    int e = blockIdx.x * blockDim.x + threadIdx.x;
    if (e < ne) atomicAdd(&g_counts[g_dst[e]], 1);
}

// Single-block exclusive scan over counts -> off, cursor; also dis = rsqrt(deg+1)
__global__ void scan_kernel(int n) {
    __shared__ int warp_sums[32];
    __shared__ int carry_s;
    int tid = threadIdx.x;
    if (tid == 0) carry_s = 0;
    __syncthreads();

    for (int base = 0; base < n; base += 1024) {
        int i = base + tid;
        int v = (i < n) ? g_counts[i] : 0;

        int x = v;
        #pragma unroll
        for (int o = 1; o < 32; o <<= 1) {
            int t = __shfl_up_sync(0xffffffffu, x, o);
            if ((tid & 31) >= o) x += t;
        }
        if ((tid & 31) == 31) warp_sums[tid >> 5] = x;
        __syncthreads();
        if (tid < 32) {
            int w = warp_sums[tid];
            int y = w;
            #pragma unroll
            for (int o = 1; o < 32; o <<= 1) {
                int t = __shfl_up_sync(0xffffffffu, y, o);
                if (tid >= o) y += t;
            }
            warp_sums[tid] = y - w;  // exclusive warp offsets
        }
        __syncthreads();

        int incl = x + warp_sums[tid >> 5] + carry_s;
        int excl = incl - v;
        if (i < n) {
            g_off[i] = excl;
            g_cursor[i] = excl;
            g_dis[i] = rsqrtf((float)v + 1.0f);
        }
        __syncthreads();
        if (tid == 1023) carry_s = incl;
        __syncthreads();
    }
    if (tid == 0) g_off[n] = carry_s;
}

__global__ void fill_kernel(int ne) {
    int e = blockIdx.x * blockDim.x + threadIdx.x;
    if (e < ne) {
        int s = g_src[e];
        int d = g_dst[e];
        int p = atomicAdd(&g_cursor[d], 1);
        if (p >= 0 && p < ne) g_csr_src[p] = s;
    }
}

// ---------------------------------------------------------------------------
// GEMM1: g_h[r] = (x[r] @ W1) * dis[r].  64-row x 64-col block tile,
// 4x4 micro-tile per thread, K=128 in two 64-chunks.
__global__ __launch_bounds__(256) void gemm1_kernel(
    const float* __restrict__ x, const float* __restrict__ W, int n)
{
    __shared__ float xs[64 * 65];   // [row][k] stride 65
    __shared__ float Ws[64 * 64];   // [k][col]

    int t = threadIdx.x;
    int row0 = blockIdx.x * 64;
    int tx = t & 15;   // col group (4 cols)
    int ty = t >> 4;   // row group (4 rows)

    float acc[4][4];
    #pragma unroll
    for (int i = 0; i < 4; ++i)
        #pragma unroll
        for (int j = 0; j < 4; ++j) acc[i][j] = 0.f;

    for (int kc = 0; kc < 2; ++kc) {
        const float* xg = x + (size_t)row0 * 128 + kc * 64;
        #pragma unroll
        for (int i = 0; i < 4; ++i) {
            int flat4 = t + i * 256;
            int r  = flat4 >> 4;
            int k4 = flat4 & 15;
            float4 v = make_float4(0.f, 0.f, 0.f, 0.f);
            if (row0 + r < n)
                v = *(const float4*)(xg + (size_t)r * 128 + k4 * 4);
            float* d = xs + r * 65 + k4 * 4;
            d[0] = v.x; d[1] = v.y; d[2] = v.z; d[3] = v.w;
        }
        const float4* wg = (const float4*)(W + (size_t)kc * 64 * 64);
        #pragma unroll
        for (int i = 0; i < 4; ++i)
            ((float4*)Ws)[t + i * 256] = wg[t + i * 256];
        __syncthreads();

        #pragma unroll 8
        for (int k = 0; k < 64; ++k) {
            float4 wv = *(const float4*)(Ws + k * 64 + tx * 4);
            float xv0 = xs[(ty * 4 + 0) * 65 + k];
            float xv1 = xs[(ty * 4 + 1) * 65 + k];
            float xv2 = xs[(ty * 4 + 2) * 65 + k];
            float xv3 = xs[(ty * 4 + 3) * 65 + k];
            acc[0][0] += xv0 * wv.x; acc[0][1] += xv0 * wv.y; acc[0][2] += xv0 * wv.z; acc[0][3] += xv0 * wv.w;
            acc[1][0] += xv1 * wv.x; acc[1][1] += xv1 * wv.y; acc[1][2] += xv1 * wv.z; acc[1][3] += xv1 * wv.w;
            acc[2][0] += xv2 * wv.x; acc[2][1] += xv2 * wv.y; acc[2][2] += xv2 * wv.z; acc[2][3] += xv2 * wv.w;
            acc[3][0] += xv3 * wv.x; acc[3][1] += xv3 * wv.y; acc[3][2] += xv3 * wv.z; acc[3][3] += xv3 * wv.w;
        }
        __syncthreads();
    }

    #pragma unroll
    for (int i = 0; i < 4; ++i) {
        int r = row0 + ty * 4 + i;
        if (r < n) {
            float dd = g_dis[r];
            float4 o = make_float4(acc[i][0] * dd, acc[i][1] * dd,
                                   acc[i][2] * dd, acc[i][3] * dd);
            *(float4*)(g_h + (size_t)r * 64 + tx * 4) = o;
        }
    }
}

// ---------------------------------------------------------------------------
// Gather layer 1: warp per dst node; lane covers cols (lane, lane+32).
__global__ void gather1_kernel(const float* __restrict__ b1, int n) {
    int w = (blockIdx.x * blockDim.x + threadIdx.x) >> 5;
    int lane = threadIdx.x & 31;
    if (w >= n) return;
    int beg = g_off[w], end = g_off[w + 1];
    float s0 = 0.f, s1 = 0.f;
    for (int j = beg; j < end; ++j) {
        int s = g_csr_src[j];
        s0 += g_h[(size_t)s * 64 + lane];
        s1 += g_h[(size_t)s * 64 + 32 + lane];
    }
    float dd = g_dis[w];
    float hd0 = g_h[(size_t)w * 64 + lane];
    float hd1 = g_h[(size_t)w * 64 + 32 + lane];
    float v0 = (s0 + hd0) * dd + b1[lane];
    float v1 = (s1 + hd1) * dd + b1[lane + 32];
    g_z[(size_t)w * 64 + lane]      = fmaxf(v0, 0.f);
    g_z[(size_t)w * 64 + 32 + lane] = fmaxf(v1, 0.f);
}

// ---------------------------------------------------------------------------
// GEMM2: g_h2[r] = (z[r] @ W2) * dis[r]. Half-warp per row (16 cols).
__global__ void gemm2_kernel(const float* __restrict__ W2, int n) {
    __shared__ float Ws[64 * 16];
    int t = threadIdx.x;
    for (int i = t; i < 64 * 16; i += blockDim.x) Ws[i] = W2[i];
    __syncthreads();

    int gw = (blockIdx.x * blockDim.x + t) >> 5;
    int lane = t & 31;
    int r = gw * 2 + (lane >> 4);
    if (r >= n) return;
    int c = lane & 15;
    float acc = 0.f;
    const float4* zr = (const float4*)(g_z + (size_t)r * 64);
    #pragma unroll
    for (int k4 = 0; k4 < 16; ++k4) {
        float4 v = zr[k4];
        acc += v.x * Ws[(k4 * 4 + 0) * 16 + c];
        acc += v.y * Ws[(k4 * 4 + 1) * 16 + c];
        acc += v.z * Ws[(k4 * 4 + 2) * 16 + c];
        acc += v.w * Ws[(k4 * 4 + 3) * 16 + c];
    }
    g_h2[(size_t)r * 16 + c] = acc * g_dis[r];
}

// ---------------------------------------------------------------------------
// Gather layer 2: warp per dst; lanes 0-15 even edges, 16-31 odd edges.
__global__ void gather2_kernel(const float* __restrict__ b2, int n) {
    int w = (blockIdx.x * blockDim.x + threadIdx.x) >> 5;
    int lane = threadIdx.x & 31;
    if (w >= n) return;
    int c  = lane & 15;
    int eh = lane >> 4;
    int beg = g_off[w], end = g_off[w + 1];
    float s = 0.f;
    for (int j = beg + eh; j < end; j += 2) {
        int sn = g_csr_src[j];
        s += g_h2[(size_t)sn * 16 + c];
    }
    s += __shfl_xor_sync(0xffffffffu, s, 16);
    if (eh == 0) {
        float dd = g_dis[w];
        float v = (s + g_h2[(size_t)w * 16 + c]) * dd + b2[c];
        g_z2[(size_t)w * 16 + c] = v;
    }
}

// ---------------------------------------------------------------------------
// Decode: logits[i] = dot16(z2[a], z2[b]) over concat(pos, neg).
__global__ void decode_kernel(const void* __restrict__ pe,
                              const void* __restrict__ ng,
                              float* __restrict__ out, int np, int nn, int n) {
    int i = blockIdx.x * blockDim.x + threadIdx.x;
    int tot = np + nn;
    if (i >= tot) return;
    int mode = g_mode;
    long long a, b;
    if (i < np) {
        if (mode) { a = ((const int*)pe)[i]; b = ((const int*)pe)[(size_t)np + i]; }
        else      { a = ((const long long*)pe)[i]; b = ((const long long*)pe)[(size_t)np + i]; }
    } else {
        int j = i - np;
        if (mode) { a = ((const int*)ng)[j]; b = ((const int*)ng)[(size_t)nn + j]; }
        else      { a = ((const long long*)ng)[j]; b = ((const long long*)ng)[(size_t)nn + j]; }
    }
    if (a < 0) a = 0; if (a >= n) a = n - 1;
    if (b < 0) b = 0; if (b >= n) b = n - 1;
    const float4* za = (const float4*)(g_z2 + (size_t)a * 16);
    const float4* zb = (const float4*)(g_z2 + (size_t)b * 16);
    float acc = 0.f;
    #pragma unroll
    for (int q = 0; q < 4; ++q) {
        float4 u = za[q], v = zb[q];
        acc += u.x * v.x + u.y * v.y + u.z * v.z + u.w * v.w;
    }
    out[i] = acc;
}

// ---------------------------------------------------------------------------
extern "C" void kernel_launch(void* const* d_in, const int* in_sizes, int n_in,
                              void* d_out, int out_size) {
    const float* x   = (const float*)d_in[0];
    const void*  ei  = d_in[1];
    const void*  pe  = d_in[2];
    const void*  ng  = d_in[3];
    const float* W1  = (const float*)d_in[4];
    const float* b1  = (const float*)d_in[5];
    const float* W2  = (const float*)d_in[6];
    const float* b2  = (const float*)d_in[7];
    float*       out = (float*)d_out;

    int n  = in_sizes[0] / 128;
    int ne = in_sizes[1] / 2;
    int np = in_sizes[2] / 2;
    int nn = in_sizes[3] / 2;

    detect_kernel<<<1, 32>>>(ei, ne, n);
    convert_kernel<<<(2 * ne + 255) / 256, 256>>>(ei, ne, n);

    zero_counts_kernel<<<(n + 255) / 256, 256>>>(n);
    count_kernel<<<(ne + 255) / 256, 256>>>(ne);
    scan_kernel<<<1, 1024>>>(n);
    fill_kernel<<<(ne + 255) / 256, 256>>>(ne);

    gemm1_kernel<<<(n + 63) / 64, 256>>>(x, W1, n);
    gather1_kernel<<<(n + 7) / 8, 256>>>(b1, n);
    {
        int warps = (n + 1) / 2;
        gemm2_kernel<<<(warps + 7) / 8, 256>>>(W2, n);
    }
    gather2_kernel<<<(n + 7) / 8, 256>>>(b2, n);
    decode_kernel<<<(np + nn + 255) / 256, 256>>>(pe, ng, out, np, nn, n);
}

// round 3
// speedup vs baseline: 1.3503x; 1.3503x over previous
#include <cuda_runtime.h>
#include <stdint.h>

#define MAX_NODES 100000
#define MAX_EDGES 3200000
#define HID 64
#define OUTD 16

// Scratch (device globals — no allocation allowed)
__device__ float g_h [MAX_NODES * HID];    // (x@W1) * dis[row]  (pre-scaled)
__device__ float g_h2[MAX_NODES * OUTD];   // (z@W2) * dis[row]  (pre-scaled)
__device__ float g_z2[MAX_NODES * OUTD];   // final embeddings
__device__ float g_dis[MAX_NODES];
__device__ int   g_counts[MAX_NODES];
__device__ int   g_off[MAX_NODES + 1];
__device__ int   g_cursor[MAX_NODES];
__device__ int   g_csr_src[MAX_EDGES];
__device__ int   g_src[MAX_EDGES];
__device__ int   g_dst[MAX_EDGES];
__device__ int   g_blocksums[128];
__device__ int   g_blockoff[128];
__device__ int   g_mode;                   // 0 = int64 indices, 1 = int32

// ---------------------------------------------------------------------------
__global__ void detect_kernel(const void* __restrict__ ei, int ne, int n) {
    if (threadIdx.x == 0 && blockIdx.x == 0) {
        const long long* p = (const long long*)ei;
        int k = ne < 256 ? ne : 256;
        int ok64 = 1;
        for (int i = 0; i < k; ++i) {
            long long v = p[i];
            if (v < 0 || v >= (long long)n) { ok64 = 0; break; }
        }
        g_mode = ok64 ? 0 : 1;
    }
}

__global__ void zero_counts_kernel(int n) {
    int i = blockIdx.x * blockDim.x + threadIdx.x;
    if (i < n) g_counts[i] = 0;
}

// Fused: normalize indices to int32 + histogram of dst.
__global__ void convert_count_kernel(const void* __restrict__ ei, int ne, int n) {
    int e = blockIdx.x * blockDim.x + threadIdx.x;
    if (e >= ne) return;
    long long s, d;
    if (g_mode) {
        s = ((const int*)ei)[e];
        d = ((const int*)ei)[(size_t)ne + e];
    } else {
        s = ((const long long*)ei)[e];
        d = ((const long long*)ei)[(size_t)ne + e];
    }
    if (s < 0) s = 0; if (s >= n) s = n - 1;
    if (d < 0) d = 0; if (d >= n) d = n - 1;
    g_src[e] = (int)s;
    g_dst[e] = (int)d;
    atomicAdd(&g_counts[(int)d], 1);
}

// ---------------------------------------------------------------------------
// 3-phase exclusive scan of counts (1024 elems per block).
__global__ void reduce_kernel(int n) {
    int t = threadIdx.x;
    int base = blockIdx.x * 1024 + t * 4;
    int s = 0;
    #pragma unroll
    for (int i = 0; i < 4; ++i) { int idx = base + i; if (idx < n) s += g_counts[idx]; }
    #pragma unroll
    for (int o = 16; o; o >>= 1) s += __shfl_down_sync(0xffffffffu, s, o);
    __shared__ int ws[8];
    if ((t & 31) == 0) ws[t >> 5] = s;
    __syncthreads();
    if (t == 0) {
        int tot = 0;
        #pragma unroll
        for (int i = 0; i < 8; ++i) tot += ws[i];
        g_blocksums[blockIdx.x] = tot;
    }
}

__global__ void scan_sums_kernel(int nb, int n) {
    __shared__ int sh[128];
    int t = threadIdx.x;  // 128 threads
    int v = (t < nb) ? g_blocksums[t] : 0;
    sh[t] = v;
    __syncthreads();
    #pragma unroll
    for (int o = 1; o < 128; o <<= 1) {
        int u = (t >= o) ? sh[t - o] : 0;
        __syncthreads();
        sh[t] += u;
        __syncthreads();
    }
    if (t < nb) g_blockoff[t] = sh[t] - v;   // exclusive
    if (t == 127) g_off[n] = sh[127];        // grand total
}

__global__ void scan_apply_kernel(int n) {
    int t = threadIdx.x;
    int base = blockIdx.x * 1024 + t * 4;
    int v[4]; int s = 0;
    #pragma unroll
    for (int i = 0; i < 4; ++i) {
        v[i] = (base + i < n) ? g_counts[base + i] : 0;
        s += v[i];
    }
    int x = s;
    #pragma unroll
    for (int o = 1; o < 32; o <<= 1) {
        int u = __shfl_up_sync(0xffffffffu, x, o);
        if ((t & 31) >= o) x += u;
    }
    __shared__ int ws[8], wo[8];
    if ((t & 31) == 31) ws[t >> 5] = x;
    __syncthreads();
    if (t == 0) {
        int r = 0;
        #pragma unroll
        for (int i = 0; i < 8; ++i) { int a = ws[i]; wo[i] = r; r += a; }
    }
    __syncthreads();
    int run = x - s + wo[t >> 5] + g_blockoff[blockIdx.x];
    #pragma unroll
    for (int i = 0; i < 4; ++i) {
        int idx = base + i;
        if (idx < n) {
            g_off[idx] = run;
            g_cursor[idx] = run;
            g_dis[idx] = rsqrtf((float)v[i] + 1.0f);
            run += v[i];
        }
    }
}

__global__ void fill_kernel(int ne) {
    int e = blockIdx.x * blockDim.x + threadIdx.x;
    if (e < ne) {
        int s = g_src[e];
        int d = g_dst[e];
        int p = atomicAdd(&g_cursor[d], 1);
        if (p >= 0 && p < ne) g_csr_src[p] = s;
    }
}

// ---------------------------------------------------------------------------
// GEMM1: g_h[r] = (x[r] @ W1) * dis[r].
__global__ __launch_bounds__(256) void gemm1_kernel(
    const float* __restrict__ x, const float* __restrict__ W, int n)
{
    __shared__ float xs[64 * 65];
    __shared__ float Ws[64 * 64];

    int t = threadIdx.x;
    int row0 = blockIdx.x * 64;
    int tx = t & 15;
    int ty = t >> 4;

    float acc[4][4];
    #pragma unroll
    for (int i = 0; i < 4; ++i)
        #pragma unroll
        for (int j = 0; j < 4; ++j) acc[i][j] = 0.f;

    for (int kc = 0; kc < 2; ++kc) {
        const float* xg = x + (size_t)row0 * 128 + kc * 64;
        #pragma unroll
        for (int i = 0; i < 4; ++i) {
            int flat4 = t + i * 256;
            int r  = flat4 >> 4;
            int k4 = flat4 & 15;
            float4 v = make_float4(0.f, 0.f, 0.f, 0.f);
            if (row0 + r < n)
                v = *(const float4*)(xg + (size_t)r * 128 + k4 * 4);
            float* d = xs + r * 65 + k4 * 4;
            d[0] = v.x; d[1] = v.y; d[2] = v.z; d[3] = v.w;
        }
        const float4* wg = (const float4*)(W + (size_t)kc * 64 * 64);
        #pragma unroll
        for (int i = 0; i < 4; ++i)
            ((float4*)Ws)[t + i * 256] = wg[t + i * 256];
        __syncthreads();

        #pragma unroll 8
        for (int k = 0; k < 64; ++k) {
            float4 wv = *(const float4*)(Ws + k * 64 + tx * 4);
            float xv0 = xs[(ty * 4 + 0) * 65 + k];
            float xv1 = xs[(ty * 4 + 1) * 65 + k];
            float xv2 = xs[(ty * 4 + 2) * 65 + k];
            float xv3 = xs[(ty * 4 + 3) * 65 + k];
            acc[0][0] += xv0 * wv.x; acc[0][1] += xv0 * wv.y; acc[0][2] += xv0 * wv.z; acc[0][3] += xv0 * wv.w;
            acc[1][0] += xv1 * wv.x; acc[1][1] += xv1 * wv.y; acc[1][2] += xv1 * wv.z; acc[1][3] += xv1 * wv.w;
            acc[2][0] += xv2 * wv.x; acc[2][1] += xv2 * wv.y; acc[2][2] += xv2 * wv.z; acc[2][3] += xv2 * wv.w;
            acc[3][0] += xv3 * wv.x; acc[3][1] += xv3 * wv.y; acc[3][2] += xv3 * wv.z; acc[3][3] += xv3 * wv.w;
        }
        __syncthreads();
    }

    #pragma unroll
    for (int i = 0; i < 4; ++i) {
        int r = row0 + ty * 4 + i;
        if (r < n) {
            float dd = g_dis[r];
            float4 o = make_float4(acc[i][0] * dd, acc[i][1] * dd,
                                   acc[i][2] * dd, acc[i][3] * dd);
            *(float4*)(g_h + (size_t)r * 64 + tx * 4) = o;
        }
    }
}

// ---------------------------------------------------------------------------
// Fused gather1 + gemm2: warp per dst node.
//   z = relu(dis[d]*(sum hhat[s] + hhat[d]) + b1)    (kept in smem row)
//   h2[d] = (z @ W2) * dis[d]                         (pre-scaled for layer 2)
__global__ __launch_bounds__(256) void gather1_gemm2_kernel(
    const float* __restrict__ b1, const float* __restrict__ W2, int n)
{
    __shared__ float W2s[64 * 16];
    __shared__ float b1s[64];
    __shared__ float zs[8][64];

    int t = threadIdx.x;
    for (int i = t; i < 64 * 16; i += 256) W2s[i] = W2[i];
    if (t < 64) b1s[t] = b1[t];
    __syncthreads();

    int w = (blockIdx.x * 256 + t) >> 5;
    int wl = t >> 5;
    int lane = t & 31;
    if (w >= n) return;

    int beg = g_off[w], end = g_off[w + 1];
    float s0 = 0.f, s1 = 0.f;
    int j = beg;
    for (; j + 1 < end; j += 2) {
        int sa = g_csr_src[j], sb = g_csr_src[j + 1];
        float a0 = g_h[(size_t)sa * 64 + lane];
        float a1 = g_h[(size_t)sa * 64 + 32 + lane];
        float c0 = g_h[(size_t)sb * 64 + lane];
        float c1 = g_h[(size_t)sb * 64 + 32 + lane];
        s0 += a0 + c0;
        s1 += a1 + c1;
    }
    if (j < end) {
        int sa = g_csr_src[j];
        s0 += g_h[(size_t)sa * 64 + lane];
        s1 += g_h[(size_t)sa * 64 + 32 + lane];
    }
    float dd = g_dis[w];
    float z0 = fmaxf((s0 + g_h[(size_t)w * 64 + lane]) * dd + b1s[lane], 0.f);
    float z1 = fmaxf((s1 + g_h[(size_t)w * 64 + 32 + lane]) * dd + b1s[lane + 32], 0.f);
    zs[wl][lane] = z0;
    zs[wl][lane + 32] = z1;
    __syncwarp();

    // gemm2 within the warp: half-warps take even/odd k (bank-disjoint W2s).
    int c = lane & 15, hf = lane >> 4;
    float acc = 0.f;
    #pragma unroll
    for (int k = 0; k < 32; ++k) {
        int kk = 2 * k + hf;
        acc += zs[wl][kk] * W2s[kk * 16 + c];
    }
    acc += __shfl_xor_sync(0xffffffffu, acc, 16);
    if (hf == 0) g_h2[(size_t)w * 16 + c] = acc * dd;
}

// ---------------------------------------------------------------------------
// Gather layer 2: warp per dst; half-warps take even/odd edges.
__global__ void gather2_kernel(const float* __restrict__ b2, int n) {
    int w = (blockIdx.x * blockDim.x + threadIdx.x) >> 5;
    int lane = threadIdx.x & 31;
    if (w >= n) return;
    int c  = lane & 15;
    int eh = lane >> 4;
    int beg = g_off[w], end = g_off[w + 1];
    float s = 0.f;
    for (int j = beg + eh; j < end; j += 2) {
        int sn = g_csr_src[j];
        s += g_h2[(size_t)sn * 16 + c];
    }
    s += __shfl_xor_sync(0xffffffffu, s, 16);
    if (eh == 0) {
        float dd = g_dis[w];
        g_z2[(size_t)w * 16 + c] = (s + g_h2[(size_t)w * 16 + c]) * dd + b2[c];
    }
}

// ---------------------------------------------------------------------------
__global__ void decode_kernel(const void* __restrict__ pe,
                              const void* __restrict__ ng,
                              float* __restrict__ out, int np, int nn, int n) {
    int i = blockIdx.x * blockDim.x + threadIdx.x;
    int tot = np + nn;
    if (i >= tot) return;
    int mode = g_mode;
    long long a, b;
    if (i < np) {
        if (mode) { a = ((const int*)pe)[i]; b = ((const int*)pe)[(size_t)np + i]; }
        else      { a = ((const long long*)pe)[i]; b = ((const long long*)pe)[(size_t)np + i]; }
    } else {
        int j = i - np;
        if (mode) { a = ((const int*)ng)[j]; b = ((const int*)ng)[(size_t)nn + j]; }
        else      { a = ((const long long*)ng)[j]; b = ((const long long*)ng)[(size_t)nn + j]; }
    }
    if (a < 0) a = 0; if (a >= n) a = n - 1;
    if (b < 0) b = 0; if (b >= n) b = n - 1;
    const float4* za = (const float4*)(g_z2 + (size_t)a * 16);
    const float4* zb = (const float4*)(g_z2 + (size_t)b * 16);
    float acc = 0.f;
    #pragma unroll
    for (int q = 0; q < 4; ++q) {
        float4 u = za[q], v = zb[q];
        acc += u.x * v.x + u.y * v.y + u.z * v.z + u.w * v.w;
    }
    out[i] = acc;
}

// ---------------------------------------------------------------------------
extern "C" void kernel_launch(void* const* d_in, const int* in_sizes, int n_in,
                              void* d_out, int out_size) {
    const float* x   = (const float*)d_in[0];
    const void*  ei  = d_in[1];
    const void*  pe  = d_in[2];
    const void*  ng  = d_in[3];
    const float* W1  = (const float*)d_in[4];
    const float* b1  = (const float*)d_in[5];
    const float* W2  = (const float*)d_in[6];
    const float* b2  = (const float*)d_in[7];
    float*       out = (float*)d_out;

    int n  = in_sizes[0] / 128;
    int ne = in_sizes[1] / 2;
    int np = in_sizes[2] / 2;
    int nn = in_sizes[3] / 2;
    int nb = (n + 1023) / 1024;

    detect_kernel<<<1, 32>>>(ei, ne, n);
    zero_counts_kernel<<<(n + 255) / 256, 256>>>(n);
    convert_count_kernel<<<(ne + 255) / 256, 256>>>(ei, ne, n);

    reduce_kernel<<<nb, 256>>>(n);
    scan_sums_kernel<<<1, 128>>>(nb, n);
    scan_apply_kernel<<<nb, 256>>>(n);
    fill_kernel<<<(ne + 255) / 256, 256>>>(ne);

    gemm1_kernel<<<(n + 63) / 64, 256>>>(x, W1, n);
    gather1_gemm2_kernel<<<(n + 7) / 8, 256>>>(b1, W2, n);
    gather2_kernel<<<(n + 7) / 8, 256>>>(b2, n);
    decode_kernel<<<(np + nn + 255) / 256, 256>>>(pe, ng, out, np, nn, n);
}

// round 4
// speedup vs baseline: 1.3949x; 1.0330x over previous
#include <cuda_runtime.h>
#include <cuda_fp16.h>
#include <stdint.h>

#define MAX_NODES 100000
#define MAX_EDGES 3200000
#define HID 64
#define OUTD 16

// Scratch (device globals — no allocation allowed)
__device__ __align__(16) __half g_h[MAX_NODES * HID];  // fp16 (x@W1)*dis[row]
__device__ float g_h2[MAX_NODES * OUTD];   // (z@W2) * dis[row]  (pre-scaled)
__device__ float g_z2[MAX_NODES * OUTD];   // final embeddings
__device__ float g_dis[MAX_NODES];
__device__ int   g_counts[MAX_NODES];
__device__ int   g_off[MAX_NODES + 1];
__device__ int   g_cursor[MAX_NODES];
__device__ int   g_csr_src[MAX_EDGES];
__device__ int   g_blocksums[128];
__device__ int   g_blockoff[128];
__device__ int   g_mode;                   // 0 = int64 indices, 1 = int32

// ---------------------------------------------------------------------------
__global__ void detect_kernel(const void* __restrict__ ei, int ne, int n) {
    if (threadIdx.x == 0 && blockIdx.x == 0) {
        const long long* p = (const long long*)ei;
        int k = ne < 256 ? ne : 256;
        int ok64 = 1;
        for (int i = 0; i < k; ++i) {
            long long v = p[i];
            if (v < 0 || v >= (long long)n) { ok64 = 0; break; }
        }
        g_mode = ok64 ? 0 : 1;
    }
}

__global__ void zero_counts_kernel(int n) {
    int i = blockIdx.x * blockDim.x + threadIdx.x;
    if (i < n) g_counts[i] = 0;
}

// Histogram of dst (reads only the dst half of edge_index).
__global__ void count_kernel(const void* __restrict__ ei, int ne, int n) {
    int e = blockIdx.x * blockDim.x + threadIdx.x;
    if (e >= ne) return;
    long long d;
    if (g_mode) d = ((const int*)ei)[(size_t)ne + e];
    else        d = ((const long long*)ei)[(size_t)ne + e];
    if (d < 0) d = 0; if (d >= n) d = n - 1;
    atomicAdd(&g_counts[(int)d], 1);
}

// ---------------------------------------------------------------------------
// 3-phase exclusive scan of counts (1024 elems per block).
__global__ void reduce_kernel(int n) {
    int t = threadIdx.x;
    int base = blockIdx.x * 1024 + t * 4;
    int s = 0;
    #pragma unroll
    for (int i = 0; i < 4; ++i) { int idx = base + i; if (idx < n) s += g_counts[idx]; }
    #pragma unroll
    for (int o = 16; o; o >>= 1) s += __shfl_down_sync(0xffffffffu, s, o);
    __shared__ int ws[8];
    if ((t & 31) == 0) ws[t >> 5] = s;
    __syncthreads();
    if (t == 0) {
        int tot = 0;
        #pragma unroll
        for (int i = 0; i < 8; ++i) tot += ws[i];
        g_blocksums[blockIdx.x] = tot;
    }
}

__global__ void scan_sums_kernel(int nb, int n) {
    __shared__ int sh[128];
    int t = threadIdx.x;  // 128 threads
    int v = (t < nb) ? g_blocksums[t] : 0;
    sh[t] = v;
    __syncthreads();
    #pragma unroll
    for (int o = 1; o < 128; o <<= 1) {
        int u = (t >= o) ? sh[t - o] : 0;
        __syncthreads();
        sh[t] += u;
        __syncthreads();
    }
    if (t < nb) g_blockoff[t] = sh[t] - v;   // exclusive
    if (t == 127) g_off[n] = sh[127];        // grand total
}

__global__ void scan_apply_kernel(int n) {
    int t = threadIdx.x;
    int base = blockIdx.x * 1024 + t * 4;
    int v[4]; int s = 0;
    #pragma unroll
    for (int i = 0; i < 4; ++i) {
        v[i] = (base + i < n) ? g_counts[base + i] : 0;
        s += v[i];
    }
    int x = s;
    #pragma unroll
    for (int o = 1; o < 32; o <<= 1) {
        int u = __shfl_up_sync(0xffffffffu, x, o);
        if ((t & 31) >= o) x += u;
    }
    __shared__ int ws[8], wo[8];
    if ((t & 31) == 31) ws[t >> 5] = x;
    __syncthreads();
    if (t == 0) {
        int r = 0;
        #pragma unroll
        for (int i = 0; i < 8; ++i) { int a = ws[i]; wo[i] = r; r += a; }
    }
    __syncthreads();
    int run = x - s + wo[t >> 5] + g_blockoff[blockIdx.x];
    #pragma unroll
    for (int i = 0; i < 4; ++i) {
        int idx = base + i;
        if (idx < n) {
            g_off[idx] = run;
            g_cursor[idx] = run;
            g_dis[idx] = rsqrtf((float)v[i] + 1.0f);
            run += v[i];
        }
    }
}

// CSR fill reading edge_index directly (both halves).
__global__ void fill_kernel(const void* __restrict__ ei, int ne, int n) {
    int e = blockIdx.x * blockDim.x + threadIdx.x;
    if (e >= ne) return;
    long long s, d;
    if (g_mode) {
        s = ((const int*)ei)[e];
        d = ((const int*)ei)[(size_t)ne + e];
    } else {
        s = ((const long long*)ei)[e];
        d = ((const long long*)ei)[(size_t)ne + e];
    }
    if (s < 0) s = 0; if (s >= n) s = n - 1;
    if (d < 0) d = 0; if (d >= n) d = n - 1;
    int p = atomicAdd(&g_cursor[(int)d], 1);
    if (p >= 0 && p < ne) g_csr_src[p] = (int)s;
}

// ---------------------------------------------------------------------------
// GEMM1: g_h[r] = fp16( (x[r] @ W1) * dis[r] ).
__global__ __launch_bounds__(256) void gemm1_kernel(
    const float* __restrict__ x, const float* __restrict__ W, int n)
{
    __shared__ float xs[64 * 65];
    __shared__ float Ws[64 * 64];

    int t = threadIdx.x;
    int row0 = blockIdx.x * 64;
    int tx = t & 15;
    int ty = t >> 4;

    float acc[4][4];
    #pragma unroll
    for (int i = 0; i < 4; ++i)
        #pragma unroll
        for (int j = 0; j < 4; ++j) acc[i][j] = 0.f;

    for (int kc = 0; kc < 2; ++kc) {
        const float* xg = x + (size_t)row0 * 128 + kc * 64;
        #pragma unroll
        for (int i = 0; i < 4; ++i) {
            int flat4 = t + i * 256;
            int r  = flat4 >> 4;
            int k4 = flat4 & 15;
            float4 v = make_float4(0.f, 0.f, 0.f, 0.f);
            if (row0 + r < n)
                v = *(const float4*)(xg + (size_t)r * 128 + k4 * 4);
            float* d = xs + r * 65 + k4 * 4;
            d[0] = v.x; d[1] = v.y; d[2] = v.z; d[3] = v.w;
        }
        const float4* wg = (const float4*)(W + (size_t)kc * 64 * 64);
        #pragma unroll
        for (int i = 0; i < 4; ++i)
            ((float4*)Ws)[t + i * 256] = wg[t + i * 256];
        __syncthreads();

        #pragma unroll 8
        for (int k = 0; k < 64; ++k) {
            float4 wv = *(const float4*)(Ws + k * 64 + tx * 4);
            float xv0 = xs[(ty * 4 + 0) * 65 + k];
            float xv1 = xs[(ty * 4 + 1) * 65 + k];
            float xv2 = xs[(ty * 4 + 2) * 65 + k];
            float xv3 = xs[(ty * 4 + 3) * 65 + k];
            acc[0][0] += xv0 * wv.x; acc[0][1] += xv0 * wv.y; acc[0][2] += xv0 * wv.z; acc[0][3] += xv0 * wv.w;
            acc[1][0] += xv1 * wv.x; acc[1][1] += xv1 * wv.y; acc[1][2] += xv1 * wv.z; acc[1][3] += xv1 * wv.w;
            acc[2][0] += xv2 * wv.x; acc[2][1] += xv2 * wv.y; acc[2][2] += xv2 * wv.z; acc[2][3] += xv2 * wv.w;
            acc[3][0] += xv3 * wv.x; acc[3][1] += xv3 * wv.y; acc[3][2] += xv3 * wv.z; acc[3][3] += xv3 * wv.w;
        }
        __syncthreads();
    }

    #pragma unroll
    for (int i = 0; i < 4; ++i) {
        int r = row0 + ty * 4 + i;
        if (r < n) {
            float dd = g_dis[r];
            __half2 h0 = __floats2half2_rn(acc[i][0] * dd, acc[i][1] * dd);
            __half2 h1 = __floats2half2_rn(acc[i][2] * dd, acc[i][3] * dd);
            __half2* dst = (__half2*)(g_h + (size_t)r * 64 + tx * 4);
            dst[0] = h0;
            dst[1] = h1;
        }
    }
}

// ---------------------------------------------------------------------------
// Fused gather1 + gemm2: warp per dst node. ĥ rows are fp16; each lane
// reads one half2 (cols 2*lane, 2*lane+1) -> one 128B transaction per edge.
__global__ __launch_bounds__(256) void gather1_gemm2_kernel(
    const float* __restrict__ b1, const float* __restrict__ W2, int n)
{
    __shared__ float W2s[64 * 16];
    __shared__ float b1s[64];
    __shared__ float zs[8][64];

    int t = threadIdx.x;
    for (int i = t; i < 64 * 16; i += 256) W2s[i] = W2[i];
    if (t < 64) b1s[t] = b1[t];
    __syncthreads();

    int w = (blockIdx.x * 256 + t) >> 5;
    int wl = t >> 5;
    int lane = t & 31;
    if (w >= n) return;

    const __half2* hh = (const __half2*)g_h;   // 32 half2 per node row
    int beg = g_off[w], end = g_off[w + 1];
    float s0 = 0.f, s1 = 0.f;
    int j = beg;
    for (; j + 3 < end; j += 4) {
        int ia = g_csr_src[j],     ib = g_csr_src[j + 1];
        int ic = g_csr_src[j + 2], id = g_csr_src[j + 3];
        float2 fa = __half22float2(hh[(size_t)ia * 32 + lane]);
        float2 fb = __half22float2(hh[(size_t)ib * 32 + lane]);
        float2 fc = __half22float2(hh[(size_t)ic * 32 + lane]);
        float2 fd = __half22float2(hh[(size_t)id * 32 + lane]);
        s0 += (fa.x + fb.x) + (fc.x + fd.x);
        s1 += (fa.y + fb.y) + (fc.y + fd.y);
    }
    for (; j < end; ++j) {
        int ia = g_csr_src[j];
        float2 fa = __half22float2(hh[(size_t)ia * 32 + lane]);
        s0 += fa.x; s1 += fa.y;
    }
    float dd = g_dis[w];
    float2 hw = __half22float2(hh[(size_t)w * 32 + lane]);
    float z0 = fmaxf((s0 + hw.x) * dd + b1s[2 * lane],     0.f);
    float z1 = fmaxf((s1 + hw.y) * dd + b1s[2 * lane + 1], 0.f);
    zs[wl][2 * lane]     = z0;
    zs[wl][2 * lane + 1] = z1;
    __syncwarp();

    // gemm2 within the warp: half-warps take even/odd k (bank-disjoint W2s).
    int c = lane & 15, hf = lane >> 4;
    float acc = 0.f;
    #pragma unroll
    for (int k = 0; k < 32; ++k) {
        int kk = 2 * k + hf;
        acc += zs[wl][kk] * W2s[kk * 16 + c];
    }
    acc += __shfl_xor_sync(0xffffffffu, acc, 16);
    if (hf == 0) g_h2[(size_t)w * 16 + c] = acc * dd;
}

// ---------------------------------------------------------------------------
// Gather layer 2: warp per dst; half-warps take even/odd edges.
__global__ void gather2_kernel(const float* __restrict__ b2, int n) {
    int w = (blockIdx.x * blockDim.x + threadIdx.x) >> 5;
    int lane = threadIdx.x & 31;
    if (w >= n) return;
    int c  = lane & 15;
    int eh = lane >> 4;
    int beg = g_off[w], end = g_off[w + 1];
    float s = 0.f;
    for (int j = beg + eh; j < end; j += 2) {
        int sn = g_csr_src[j];
        s += g_h2[(size_t)sn * 16 + c];
    }
    s += __shfl_xor_sync(0xffffffffu, s, 16);
    if (eh == 0) {
        float dd = g_dis[w];
        g_z2[(size_t)w * 16 + c] = (s + g_h2[(size_t)w * 16 + c]) * dd + b2[c];
    }
}

// ---------------------------------------------------------------------------
__global__ void decode_kernel(const void* __restrict__ pe,
                              const void* __restrict__ ng,
                              float* __restrict__ out, int np, int nn, int n) {
    int i = blockIdx.x * blockDim.x + threadIdx.x;
    int tot = np + nn;
    if (i >= tot) return;
    int mode = g_mode;
    long long a, b;
    if (i < np) {
        if (mode) { a = ((const int*)pe)[i]; b = ((const int*)pe)[(size_t)np + i]; }
        else      { a = ((const long long*)pe)[i]; b = ((const long long*)pe)[(size_t)np + i]; }
    } else {
        int j = i - np;
        if (mode) { a = ((const int*)ng)[j]; b = ((const int*)ng)[(size_t)nn + j]; }
        else      { a = ((const long long*)ng)[j]; b = ((const long long*)ng)[(size_t)nn + j]; }
    }
    if (a < 0) a = 0; if (a >= n) a = n - 1;
    if (b < 0) b = 0; if (b >= n) b = n - 1;
    const float4* za = (const float4*)(g_z2 + (size_t)a * 16);
    const float4* zb = (const float4*)(g_z2 + (size_t)b * 16);
    float acc = 0.f;
    #pragma unroll
    for (int q = 0; q < 4; ++q) {
        float4 u = za[q], v = zb[q];
        acc += u.x * v.x + u.y * v.y + u.z * v.z + u.w * v.w;
    }
    out[i] = acc;
}

// ---------------------------------------------------------------------------
extern "C" void kernel_launch(void* const* d_in, const int* in_sizes, int n_in,
                              void* d_out, int out_size) {
    const float* x   = (const float*)d_in[0];
    const void*  ei  = d_in[1];
    const void*  pe  = d_in[2];
    const void*  ng  = d_in[3];
    const float* W1  = (const float*)d_in[4];
    const float* b1  = (const float*)d_in[5];
    const float* W2  = (const float*)d_in[6];
    const float* b2  = (const float*)d_in[7];
    float*       out = (float*)d_out;

    int n  = in_sizes[0] / 128;
    int ne = in_sizes[1] / 2;
    int np = in_sizes[2] / 2;
    int nn = in_sizes[3] / 2;
    int nb = (n + 1023) / 1024;

    detect_kernel<<<1, 32>>>(ei, ne, n);
    zero_counts_kernel<<<(n + 255) / 256, 256>>>(n);
    count_kernel<<<(ne + 255) / 256, 256>>>(ei, ne, n);

    reduce_kernel<<<nb, 256>>>(n);
    scan_sums_kernel<<<1, 128>>>(nb, n);
    scan_apply_kernel<<<nb, 256>>>(n);
    fill_kernel<<<(ne + 255) / 256, 256>>>(ei, ne, n);

    gemm1_kernel<<<(n + 63) / 64, 256>>>(x, W1, n);
    gather1_gemm2_kernel<<<(n + 7) / 8, 256>>>(b1, W2, n);
    gather2_kernel<<<(n + 7) / 8, 256>>>(b2, n);
    decode_kernel<<<(np + nn + 255) / 256, 256>>>(pe, ng, out, np, nn, n);
}